// round 1
// baseline (speedup 1.0000x reference)
#include <cuda_runtime.h>
#include <cuda_bf16.h>

#define SEQ    32768
#define WD     512
#define HID    1024
#define NCTA   32          // CTAs per fold
#define NFOLD  2
#define RPC    16          // rows of W1/W3 per CTA; cols of W2 per CTA (= WD/NCTA)
#define THREADS 256

struct Smem {
    float W1s[RPC][HID];     // 64 KB  W1 row slice  [local row][col over h=(p,x)]
    float W2s[RPC][HID];     // 64 KB  W2 col slice, transposed: W2s[local c][t-row]
    float W3s[RPC][HID];     // 64 KB  W3 row slice
    float u_s[HID];          // tanh(t + b2)
    float b2s[HID];
    float p_s[WD];
    float x_s[2][WD];        // double-buffered x_i
    float a_s[RPC];
    float b1s[RPC];
    float b3s[RPC];
};

__device__ float        g_t[NFOLD][2][HID];     // double-buffered t accumulators
__device__ float        g_pv[NFOLD][WD];        // shared p vector
__device__ unsigned int g_flags[NFOLD * NCTA * 32];  // 128B-strided epoch flags

__global__ void __launch_bounds__(THREADS, 1)
rnn_fold_kernel(const float* __restrict__ input,
                const float* __restrict__ input2,
                const float* __restrict__ W1g, const float* __restrict__ b1g,
                const float* __restrict__ W2g, const float* __restrict__ b2g,
                const float* __restrict__ W3g, const float* __restrict__ b3g)
{
    extern __shared__ float smem_raw[];
    Smem& s = *reinterpret_cast<Smem*>(smem_raw);

    const int tid  = threadIdx.x;
    const int lane = tid & 31;
    const int warp = tid >> 5;
    const int cta  = blockIdx.x;
    const int fold = cta / NCTA;
    const int k    = cta % NCTA;
    const int r0   = k * RPC;
    const float* xsrc = (fold == 0) ? input : input2;

    // ---------------- load resident weight slices ----------------
    {
        const float4* src1 = reinterpret_cast<const float4*>(W1g + (size_t)r0 * HID);
        float4*       dst1 = reinterpret_cast<float4*>(&s.W1s[0][0]);
        const float4* src3 = reinterpret_cast<const float4*>(W3g + (size_t)r0 * HID);
        float4*       dst3 = reinterpret_cast<float4*>(&s.W3s[0][0]);
        for (int i = tid; i < RPC * HID / 4; i += THREADS) { dst1[i] = src1[i]; dst3[i] = src3[i]; }

        const int c0 = k * RPC;
        for (int r = tid; r < HID; r += THREADS) {
            const float4* wr = reinterpret_cast<const float4*>(W2g + (size_t)r * WD + c0);
            #pragma unroll
            for (int q = 0; q < 4; ++q) {
                float4 v = wr[q];
                s.W2s[4*q+0][r] = v.x; s.W2s[4*q+1][r] = v.y;
                s.W2s[4*q+2][r] = v.z; s.W2s[4*q+3][r] = v.w;
            }
        }
        for (int i = tid; i < HID; i += THREADS) s.b2s[i] = b2g[i];
        if (tid < RPC) { s.b1s[tid] = b1g[r0 + tid]; s.b3s[tid] = b3g[r0 + tid]; }

        // p0 = x[0]; x buffer 1 = x[1]
        for (int i = tid; i < WD / 2; i += THREADS) {
            reinterpret_cast<float2*>(s.p_s)[i]    = reinterpret_cast<const float2*>(xsrc)[i];
            reinterpret_cast<float2*>(s.x_s[1])[i] = reinterpret_cast<const float2*>(xsrc + WD)[i];
        }
        // zero both t accumulator buffers (our chunk)
        if (tid < HID / NCTA) {
            g_t[fold][0][k * (HID / NCTA) + tid] = 0.0f;
            g_t[fold][1][k * (HID / NCTA) + tid] = 0.0f;
        }
    }

    const unsigned int my_slot   = (unsigned)(fold * NCTA + k) * 32u;
    const unsigned int fold_base = (unsigned)(fold * NCTA) * 32u;
    // monotonic epoch base: equal across all CTAs at launch start (replay-safe)
    const unsigned int base = *(volatile unsigned int*)&g_flags[my_slot];

    auto grid_barrier = [&](unsigned int target) {
        __threadfence();
        __syncthreads();
        if (tid == 0) *(volatile unsigned int*)&g_flags[my_slot] = target;
        if (warp == 0) {
            volatile unsigned int* fp = &g_flags[fold_base + (unsigned)lane * 32u];
            unsigned int v;
            do { v = *fp; } while ((int)(v - target) < 0);
            __threadfence();
        }
        __syncthreads();
    };

    unsigned int ep = base + 1u;
    grid_barrier(ep);      // init barrier: t-accumulator zeroing visible fold-wide
    ++ep;

    const int row = warp * 2 + (lane >> 4);   // local W1/W3 output row for this thread
    const int lg  = lane & 15;                // lane within 16-lane dot group

    for (int i = 1; i < SEQ; ++i) {
        const int buf = i & 1;

        // ---------------- stage 1: a = relu(W1 [p;x_i] + b1) (row slice) ----------------
        {
            const float4* w1r = reinterpret_cast<const float4*>(&s.W1s[row][0]);
            const float4* pp  = reinterpret_cast<const float4*>(s.p_s);
            const float4* xx  = reinterpret_cast<const float4*>(s.x_s[buf]);
            float acc = 0.0f;
            #pragma unroll
            for (int q = 0; q < 8; ++q) {          // h = p part (chunks 0..127)
                int j = lg + 16 * q;
                float4 w = w1r[j]; float4 h = pp[j];
                acc += w.x*h.x + w.y*h.y + w.z*h.z + w.w*h.w;
            }
            #pragma unroll
            for (int q = 8; q < 16; ++q) {         // h = x part (chunks 128..255)
                int j = lg + 16 * q;
                float4 w = w1r[j]; float4 h = xx[j - 128];
                acc += w.x*h.x + w.y*h.y + w.z*h.z + w.w*h.w;
            }
            acc += __shfl_down_sync(0xffffffffu, acc, 8);
            acc += __shfl_down_sync(0xffffffffu, acc, 4);
            acc += __shfl_down_sync(0xffffffffu, acc, 2);
            acc += __shfl_down_sync(0xffffffffu, acc, 1);
            if (lg == 0) s.a_s[row] = fmaxf(acc + s.b1s[row], 0.0f);
        }
        __syncthreads();

        // prefetch next x row into the other buffer (consumed next iteration)
        if (i + 1 < SEQ) {
            reinterpret_cast<float2*>(s.x_s[(i + 1) & 1])[tid] =
                reinterpret_cast<const float2*>(xsrc + (size_t)(i + 1) * WD)[tid];
        }
        // zero the t buffer for step i+1 (safe: all reads of it finished before
        // barrier-2 of step i-1; visibility fenced by barrier-1 below)
        if (tid < HID / NCTA) g_t[fold][(i + 1) & 1][k * (HID / NCTA) + tid] = 0.0f;

        // ---------------- stage 1b: partial t += W2[:, our 16 cols] @ a_slice ----------------
        {
            const int rb = ((tid + (k << 3)) & 255);   // staggered per-CTA to spread atomics
            float4 pt = make_float4(0.f, 0.f, 0.f, 0.f);
            #pragma unroll
            for (int c = 0; c < RPC; ++c) {
                float av = s.a_s[c];                    // LDS broadcast
                float4 w = reinterpret_cast<const float4*>(&s.W2s[c][0])[rb];
                pt.x += w.x * av; pt.y += w.y * av; pt.z += w.z * av; pt.w += w.w * av;
            }
            float* tg = &g_t[fold][buf][0] + rb * 4;
            atomicAdd(tg + 0, pt.x); atomicAdd(tg + 1, pt.y);
            atomicAdd(tg + 2, pt.z); atomicAdd(tg + 3, pt.w);
        }

        grid_barrier(ep); ++ep;   // barrier 1: t fully reduced

        // ---------------- stage 2: u = tanh(t + b2); p = tanh(W3 u + b3) (row slice) ----------------
        {
            float4 t4  = __ldcg(reinterpret_cast<const float4*>(&g_t[fold][buf][0]) + tid);
            float4 b24 = reinterpret_cast<const float4*>(s.b2s)[tid];
            float4 u4;
            u4.x = tanhf(t4.x + b24.x); u4.y = tanhf(t4.y + b24.y);
            u4.z = tanhf(t4.z + b24.z); u4.w = tanhf(t4.w + b24.w);
            reinterpret_cast<float4*>(s.u_s)[tid] = u4;
        }
        __syncthreads();
        {
            const float4* w3r = reinterpret_cast<const float4*>(&s.W3s[row][0]);
            const float4* uu  = reinterpret_cast<const float4*>(s.u_s);
            float acc = 0.0f;
            #pragma unroll
            for (int q = 0; q < 16; ++q) {
                int j = lg + 16 * q;
                float4 w = w3r[j]; float4 h = uu[j];
                acc += w.x*h.x + w.y*h.y + w.z*h.z + w.w*h.w;
            }
            acc += __shfl_down_sync(0xffffffffu, acc, 8);
            acc += __shfl_down_sync(0xffffffffu, acc, 4);
            acc += __shfl_down_sync(0xffffffffu, acc, 2);
            acc += __shfl_down_sync(0xffffffffu, acc, 1);
            if (lg == 0) g_pv[fold][r0 + row] = tanhf(acc + s.b3s[row]);
        }

        if (i < SEQ - 1) {
            grid_barrier(ep); ++ep;   // barrier 2: full p available
            reinterpret_cast<float2*>(s.p_s)[tid] =
                __ldcg(reinterpret_cast<const float2*>(&g_pv[fold][0]) + tid);
            __syncthreads();
        }
    }
}

__global__ void logits_kernel(const float* __restrict__ W4g,
                              const float* __restrict__ b4g,
                              float* __restrict__ out)
{
    __shared__ float lg[5];
    const int tid = threadIdx.x, warp = tid >> 5, lane = tid & 31;
    if (warp < 5) {
        float acc = 0.0f;
        const float* w = W4g + warp * (2 * WD);
        for (int j = lane; j < 2 * WD; j += 32) {
            float h = (j < WD) ? g_pv[0][j] : g_pv[1][j - WD];
            acc += w[j] * h;
        }
        #pragma unroll
        for (int o = 16; o > 0; o >>= 1) acc += __shfl_down_sync(0xffffffffu, acc, o);
        if (lane == 0) lg[warp] = acc + b4g[warp];
    }
    __syncthreads();
    if (tid == 0) {
        float m = lg[0];
        #pragma unroll
        for (int c = 1; c < 5; ++c) m = fmaxf(m, lg[c]);
        float ssum = 0.0f;
        #pragma unroll
        for (int c = 0; c < 5; ++c) ssum += expf(lg[c] - m);
        float lse = m + logf(ssum);
        #pragma unroll
        for (int c = 0; c < 5; ++c) out[c] = lg[c] - lse;
    }
}

extern "C" void kernel_launch(void* const* d_in, const int* in_sizes, int n_in,
                              void* d_out, int out_size)
{
    const float* input  = (const float*)d_in[0];
    const float* input2 = (const float*)d_in[1];
    // inputs: input, input2, [word_dim scalar], W1, b1, W2, b2, W3, b3, W4, b4
    const int off = (n_in >= 11) ? 3 : 2;
    const float* W1 = (const float*)d_in[off + 0];
    const float* b1 = (const float*)d_in[off + 1];
    const float* W2 = (const float*)d_in[off + 2];
    const float* b2 = (const float*)d_in[off + 3];
    const float* W3 = (const float*)d_in[off + 4];
    const float* b3 = (const float*)d_in[off + 5];
    const float* W4 = (const float*)d_in[off + 6];
    const float* b4 = (const float*)d_in[off + 7];

    cudaFuncSetAttribute(rnn_fold_kernel,
                         cudaFuncAttributeMaxDynamicSharedMemorySize,
                         (int)sizeof(Smem));
    rnn_fold_kernel<<<NFOLD * NCTA, THREADS, sizeof(Smem)>>>(
        input, input2, W1, b1, W2, b2, W3, b3);
    logits_kernel<<<1, 160>>>(W4, b4, (float*)d_out);
}